// round 7
// baseline (speedup 1.0000x reference)
#include <cuda_runtime.h>
#include <math.h>
#include <stdint.h>

#define BATCH 32
#define SEQ   1024
#define DIN   128
#define HID   256
#define G4    1024   // 4*H
#define H2    512    // 2*H

// ---------------- scratch (device globals; no allocation allowed) ----------------
__device__ float  g_xpf[(size_t)BATCH * SEQ * G4];   // 128 MB
__device__ float  g_xpb[(size_t)BATCH * SEQ * G4];   // 128 MB
__device__ float  g_h0 [(size_t)BATCH * SEQ * H2];   // 64 MB
__device__ float  g_h1 [(size_t)BATCH * SEQ * H2];   // 64 MB
__device__ float  g_ctx[(size_t)BATCH * SEQ * H2];   // 64 MB
__device__ float  g_e  [BATCH * SEQ];

// ---------------- helpers ----------------
__device__ __forceinline__ uint32_t smem_u32(const void* p) {
    uint32_t a;
    asm("{ .reg .u64 t; cvta.to.shared.u64 t, %1; cvt.u32.u64 %0, t; }" : "=r"(a) : "l"(p));
    return a;
}
__device__ __forceinline__ uint32_t cvt_tf32(float x) {
    uint32_t r; asm("cvt.rna.tf32.f32 %0, %1;" : "=r"(r) : "f"(x)); return r;
}
__device__ __forceinline__ void mma8(float* d, const uint32_t* a, const uint32_t* b) {
    asm volatile("mma.sync.aligned.m16n8k8.row.col.f32.tf32.tf32.f32 "
        "{%0,%1,%2,%3}, {%4,%5,%6,%7}, {%8,%9}, {%0,%1,%2,%3};"
        : "+f"(d[0]), "+f"(d[1]), "+f"(d[2]), "+f"(d[3])
        : "r"(a[0]), "r"(a[1]), "r"(a[2]), "r"(a[3]), "r"(b[0]), "r"(b[1]));
}

// ---------------- tf32 split-precision GEMM via mma.sync ----------------
// C[m*Nld+n] = bias[n] + sum_k A[m*K+k] * W[n*K+k]
// 128x128 tile / CTA, K-chunks of 32, 512 threads (16 warps, each 32x32 tile).
// SMEM: 2 buffers x { A_hi, A_lo, B_hi, B_lo : 4096 u32 each } = 128KB.
#define BUF_U32   16384
#define GEMM_SMEM (2 * 65536)

__device__ __forceinline__ void g_ldg(const float* __restrict__ A, const float* __restrict__ W,
                                      int m0, int n0, int K, int kbase, int tid,
                                      float4* aR, float4* bR) {
#pragma unroll
    for (int i = 0; i < 2; i++) {
        int lin = tid + i * 512;
        int row = lin >> 3, cg = lin & 7;
        aR[i] = *(const float4*)&A[(size_t)(m0 + row) * K + kbase + cg * 4];
        bR[i] = *(const float4*)&W[(size_t)(n0 + row) * K + kbase + cg * 4];
    }
}

__device__ __forceinline__ void g_stage(uint32_t* buf, const float4* aR, const float4* bR, int tid) {
    uint32_t* Ah = buf;
    uint32_t* Al = buf + 4096;
    uint32_t* Bh = buf + 8192;
    uint32_t* Bl = buf + 12288;
#pragma unroll
    for (int i = 0; i < 2; i++) {
        int lin = tid + i * 512;
        int row = lin >> 3, cg = lin & 7;
        float av[4] = { aR[i].x, aR[i].y, aR[i].z, aR[i].w };
        float wv[4] = { bR[i].x, bR[i].y, bR[i].z, bR[i].w };
#pragma unroll
        for (int j = 0; j < 4; j++) {
            int col = cg * 4 + j;
            int ks = col >> 3, c8 = col & 7, tig = c8 & 3, half = c8 >> 2;
            int lane = ((row & 7) << 2) | tig;
            int regA = ((row >> 3) & 1) | (half << 1);
            int idxA = ((ks * 8 + (row >> 4)) * 32 + lane) * 4 + regA;
            uint32_t hi = cvt_tf32(av[j]);
            uint32_t lo = cvt_tf32(av[j] - __uint_as_float(hi));
            Ah[idxA] = hi; Al[idxA] = lo;
            int idxB = ((ks * 16 + (row >> 3)) * 32 + lane) * 2 + half;
            hi = cvt_tf32(wv[j]);
            lo = cvt_tf32(wv[j] - __uint_as_float(hi));
            Bh[idxB] = hi; Bl[idxB] = lo;
        }
    }
}

__global__ void __launch_bounds__(512, 1) mma_gemm(const float* __restrict__ A,
                                                   const float* __restrict__ W,
                                                   const float* __restrict__ bias,
                                                   float* __restrict__ C,
                                                   int Nld, int K) {
    extern __shared__ uint32_t sm[];
    int tid = threadIdx.x;
    int lane = tid & 31;
    int warp = tid >> 5;
    int wm = warp >> 2, wn = warp & 3;  // 4x4 warp grid, each 32x32
    int m0 = blockIdx.x * 128, n0 = blockIdx.y * 128;

    float acc[2][4][4];
#pragma unroll
    for (int a = 0; a < 2; a++)
#pragma unroll
        for (int b = 0; b < 4; b++)
#pragma unroll
            for (int c = 0; c < 4; c++) acc[a][b][c] = 0.f;

    float4 aR[2], bR[2];
    g_ldg(A, W, m0, n0, K, 0, tid, aR, bR);
    g_stage(sm, aR, bR, tid);
    __syncthreads();

    const int KT = K / 32;
    for (int kt = 0; kt < KT; kt++) {
        if (kt + 1 < KT) g_ldg(A, W, m0, n0, K, (kt + 1) * 32, tid, aR, bR);

        const uint32_t* buf = sm + (kt & 1) * BUF_U32;
        const uint32_t* Ah = buf;
        const uint32_t* Al = buf + 4096;
        const uint32_t* Bh = buf + 8192;
        const uint32_t* Bl = buf + 12288;
#pragma unroll
        for (int ks = 0; ks < 4; ks++) {
            uint32_t fAh[2][4], fAl[2][4], fBh[4][2], fBl[4][2];
#pragma unroll
            for (int mf = 0; mf < 2; mf++) {
                uint4 v = *(const uint4*)&Ah[((ks * 8 + wm * 2 + mf) * 32 + lane) * 4];
                fAh[mf][0] = v.x; fAh[mf][1] = v.y; fAh[mf][2] = v.z; fAh[mf][3] = v.w;
                uint4 u = *(const uint4*)&Al[((ks * 8 + wm * 2 + mf) * 32 + lane) * 4];
                fAl[mf][0] = u.x; fAl[mf][1] = u.y; fAl[mf][2] = u.z; fAl[mf][3] = u.w;
            }
#pragma unroll
            for (int nf = 0; nf < 4; nf++) {
                uint2 v = *(const uint2*)&Bh[((ks * 16 + wn * 4 + nf) * 32 + lane) * 2];
                fBh[nf][0] = v.x; fBh[nf][1] = v.y;
                uint2 u = *(const uint2*)&Bl[((ks * 16 + wn * 4 + nf) * 32 + lane) * 2];
                fBl[nf][0] = u.x; fBl[nf][1] = u.y;
            }
#pragma unroll
            for (int mf = 0; mf < 2; mf++)
#pragma unroll
                for (int nf = 0; nf < 4; nf++) {
                    mma8(acc[mf][nf], fAh[mf], fBh[nf]);
                    mma8(acc[mf][nf], fAh[mf], fBl[nf]);
                    mma8(acc[mf][nf], fAl[mf], fBh[nf]);
                }
        }
        if (kt + 1 < KT) g_stage(sm + ((kt + 1) & 1) * BUF_U32, aR, bR, tid);
        __syncthreads();
    }

    int g = lane >> 2, tig = lane & 3;
#pragma unroll
    for (int mf = 0; mf < 2; mf++) {
#pragma unroll
        for (int nf = 0; nf < 4; nf++) {
            int row = m0 + wm * 32 + mf * 16 + g;
            int col = n0 + wn * 32 + nf * 8 + tig * 2;
            float b0 = bias[col], b1 = bias[col + 1];
            float2 v0 = make_float2(acc[mf][nf][0] + b0, acc[mf][nf][1] + b1);
            float2 v1 = make_float2(acc[mf][nf][2] + b0, acc[mf][nf][3] + b1);
            *(float2*)&C[(size_t)row * Nld + col]       = v0;
            *(float2*)&C[(size_t)(row + 8) * Nld + col] = v1;
        }
    }
}

// ---------------- f32x2 packed-FMA helpers ----------------
__device__ __forceinline__ unsigned long long ffma2(unsigned long long a,
                                                    unsigned long long b,
                                                    unsigned long long c) {
    unsigned long long d;
    asm("fma.rn.f32x2 %0, %1, %2, %3;" : "=l"(d) : "l"(a), "l"(b), "l"(c));
    return d;
}
__device__ __forceinline__ void unpack2(unsigned long long v, float& x, float& y) {
    asm("mov.b64 {%0, %1}, %2;" : "=f"(x), "=f"(y) : "l"(v));
}
__device__ __forceinline__ float sigm_fast(float x) { return 1.f / (1.f + __expf(-x)); }
__device__ __forceinline__ float tanh_fast(float x) { return 2.f / (1.f + __expf(-2.f * x)) - 1.f; }

// ---------------- clustered LSTM scan v3 ----------------
// Cluster of 8 CTAs (unit slices) per (dir, batch-group of 4). 256 threads/CTA:
// tid -> kh = tid&1 (k half), u = (tid>>1)&31 (local unit), b = tid>>6 (local batch).
// Weights resident in SMEM as gate-pair float4: slot (kp*2+gp)*32+u holds
//   gp=0: {w_i[2kp], w_i[2kp+1], w_f[2kp], w_f[2kp+1]} for unit ug
//   gp=1: same for gates g,o.   (kp = global k-pair 0..127)
// h double buffer: [2][4b][256k] floats at SMEM_H_OFF. Split arrive/wait barrier.
#define SMEM_H_OFF   131072
#define SCAN_SMEM    139264

__global__ void __launch_bounds__(256, 1) __cluster_dims__(8, 1, 1)
lstm_scan_cl(const float* __restrict__ xpf,
             const float* __restrict__ xpb,
             const float* __restrict__ whh_f,
             const float* __restrict__ whh_b,
             float* __restrict__ out) {
    extern __shared__ char smem[];
    uint32_t smem_base = smem_u32(smem);

    int slice = blockIdx.x;           // 0..7 cluster rank = unit slice
    int bg    = blockIdx.y;           // 0..7 batch group (4 batches)
    int d     = blockIdx.z;           // 0 fw, 1 bw
    const float* xp = d ? xpb : xpf;
    const float* W  = d ? whh_b : whh_f;

    int tid = threadIdx.x;
    int kh = tid & 1;                 // k half: [kh*128, kh*128+128)
    int u  = (tid >> 1) & 31;         // local unit
    int b  = tid >> 6;                // local batch 0..3
    int ug = slice * 32 + u;
    int bglob = bg * 4 + b;

    // ---- load resident weight slice (once): 8192 float4 slots ----
    float4* wsh = (float4*)smem;
    for (int i = tid; i < 8192; i += 256) {
        int uu = i & 31;
        int gp = (i >> 5) & 1;
        int kp = i >> 6;
        int r0 = (gp * 2) * HID + slice * 32 + uu;       // gate i or g
        int r1 = (gp * 2 + 1) * HID + slice * 32 + uu;   // gate f or o
        float2 w0 = *(const float2*)&W[(size_t)r0 * HID + 2 * kp];
        float2 w1 = *(const float2*)&W[(size_t)r1 * HID + 2 * kp];
        wsh[i] = make_float4(w0.x, w0.y, w1.x, w1.y);
    }
    // ---- zero h buffers ----
    float* hsh = (float*)(smem + SMEM_H_OFF);
    for (int i = tid; i < 2048; i += 256) hsh[i] = 0.f;
    __syncthreads();

    // precompute remote push addresses (mapa hoisted out of time loop)
    uint32_t ra[8];
    {
        uint32_t la = smem_base + SMEM_H_OFF + (uint32_t)((b * 256 + ug) * 4);
#pragma unroll
        for (int cta = 0; cta < 8; cta++)
            asm("mapa.shared::cluster.u32 %0, %1, %2;" : "=r"(ra[cta]) : "r"(la), "r"(cta));
    }

    // initial full cluster sync: buffers zeroed everywhere
    asm volatile("barrier.cluster.arrive.aligned;" ::: "memory");
    asm volatile("barrier.cluster.wait.aligned;" ::: "memory");

    const unsigned long long* wq = (const unsigned long long*)smem;
    float c = 0.f;

    for (int t = 0; t < SEQ; t++) {
        int s = d ? (SEQ - 1 - t) : t;
        const float* xr = xp + ((size_t)bglob * SEQ + s) * G4;
        float xi = xr[ug];
        float xf = xr[ug + 256];
        float xg = xr[ug + 512];
        float xo = xr[ug + 768];

        if (t) asm volatile("barrier.cluster.wait.aligned;" ::: "memory");

        // k-loop over this thread's half: 32 float4 h loads, 128 weight LDS.128
        const float4* hv4 = (const float4*)(smem + SMEM_H_OFF + (t & 1) * 4096 +
                                            (b * 1024 + kh * 512));
        // weight u64 base: slot (kp*2+gp)*32+u as u64 pairs -> u64 index ((kp*2+gp)*32+u)*2
        const unsigned long long* wk = wq + ((size_t)(kh * 64) * 2 * 32 + u) * 2;

        unsigned long long aI = 0ull, aF = 0ull, aG = 0ull, aO = 0ull;
#pragma unroll 4
        for (int j = 0; j < 32; j++) {
            float4 hv = hv4[j];
            unsigned long long h2a = *(const unsigned long long*)&hv.x;
            unsigned long long h2b = *(const unsigned long long*)&hv.z;
            // kp pair 2j: gp0, gp1 ; kp pair 2j+1: gp0, gp1
            const unsigned long long* w0 = wk + (size_t)(4 * j) * 64;       // (2j)*2+0
            const unsigned long long* w1 = wk + (size_t)(4 * j + 1) * 64;   // (2j)*2+1
            const unsigned long long* w2 = wk + (size_t)(4 * j + 2) * 64;   // (2j+1)*2+0
            const unsigned long long* w3 = wk + (size_t)(4 * j + 3) * 64;   // (2j+1)*2+1
            aI = ffma2(h2a, w0[0], aI);
            aF = ffma2(h2a, w0[1], aF);
            aG = ffma2(h2a, w1[0], aG);
            aO = ffma2(h2a, w1[1], aO);
            aI = ffma2(h2b, w2[0], aI);
            aF = ffma2(h2b, w2[1], aF);
            aG = ffma2(h2b, w3[0], aG);
            aO = ffma2(h2b, w3[1], aO);
        }
        float lo, hi;
        unpack2(aI, lo, hi); float sI = lo + hi;
        unpack2(aF, lo, hi); float sF = lo + hi;
        unpack2(aG, lo, hi); float sG = lo + hi;
        unpack2(aO, lo, hi); float sO = lo + hi;
        // combine k-halves (partner lane differs in kh bit = lane^1)
        sI += __shfl_xor_sync(0xFFFFFFFFu, sI, 1);
        sF += __shfl_xor_sync(0xFFFFFFFFu, sF, 1);
        sG += __shfl_xor_sync(0xFFFFFFFFu, sG, 1);
        sO += __shfl_xor_sync(0xFFFFFFFFu, sO, 1);

        float ig = sigm_fast(xi + sI);
        float fg = sigm_fast(xf + sF);
        float gg = tanh_fast(xg + sG);
        float og = sigm_fast(xo + sO);
        c = fg * c + ig * gg;
        float h = og * tanh_fast(c);

        if (kh == 0) {
            uint32_t bo = (uint32_t)(((t + 1) & 1) * 4096);
#pragma unroll
            for (int cta = 0; cta < 8; cta++)
                asm volatile("st.shared::cluster.f32 [%0], %1;"
                             :: "r"(ra[cta] + bo), "f"(h) : "memory");
            out[((size_t)bglob * SEQ + s) * H2 + d * HID + ug] = h;
        }
        asm volatile("barrier.cluster.arrive.aligned;" ::: "memory");
    }
    asm volatile("barrier.cluster.wait.aligned;" ::: "memory");
}

// ---------------- attention scores -> e = exp(s - max_t s) ----------------
__global__ void __launch_bounds__(256) attn_scores(const float* __restrict__ h,
                                                   const float* __restrict__ attn_w,
                                                   const float* __restrict__ attn_b,
                                                   float* __restrict__ e_out) {
    int b = blockIdx.x;
    int tid = threadIdx.x;
    __shared__ float sc[SEQ];
    __shared__ float red[256];
    __shared__ float wsh[H2];
    wsh[tid]       = attn_w[tid];
    wsh[tid + 256] = attn_w[tid + 256];
    __syncthreads();
    float ab = attn_b[0];
    float mx = -1e30f;
    for (int t = tid; t < SEQ; t += 256) {
        const float* hr = h + ((size_t)b * SEQ + t) * H2;
        float acc = 0.f;
#pragma unroll 4
        for (int cch = 0; cch < H2; cch += 4) {
            float4 hv = *(const float4*)&hr[cch];
            acc += hv.x * wsh[cch] + hv.y * wsh[cch + 1] + hv.z * wsh[cch + 2] + hv.w * wsh[cch + 3];
        }
        acc += ab;
        sc[t] = acc;
        mx = fmaxf(mx, acc);
    }
    red[tid] = mx;
    __syncthreads();
    for (int s = 128; s > 0; s >>= 1) {
        if (tid < s) red[tid] = fmaxf(red[tid], red[tid + s]);
        __syncthreads();
    }
    mx = red[0];
    for (int t = tid; t < SEQ; t += 256)
        e_out[b * SEQ + t] = expf(sc[t] - mx);
}

// ---------------- running-softmax context (4-way channel split) ----------------
__global__ void __launch_bounds__(128) ctx_kernel(const float* __restrict__ h,
                                                  const float* __restrict__ e,
                                                  float* __restrict__ ctx) {
    int b = blockIdx.x;
    int ch = blockIdx.y * 128 + threadIdx.x;
    const float* eb = e + b * SEQ;
    float num = 0.f, den = 0.f;
    for (int t = 0; t < SEQ; t++) {
        float et = eb[t];
        den += et;
        size_t off = ((size_t)b * SEQ + t) * H2 + ch;
        num += et * h[off];
        ctx[off] = num / den;
    }
}

// ---------------- launch ----------------
extern "C" void kernel_launch(void* const* d_in, const int* in_sizes, int n_in,
                              void* d_out, int out_size) {
    const float* x        = (const float*)d_in[0];
    const float* w_ih_l0f = (const float*)d_in[1];
    const float* w_hh_l0f = (const float*)d_in[2];
    const float* b_l0f    = (const float*)d_in[3];
    const float* w_ih_l0b = (const float*)d_in[4];
    const float* w_hh_l0b = (const float*)d_in[5];
    const float* b_l0b    = (const float*)d_in[6];
    const float* w_ih_l1f = (const float*)d_in[7];
    const float* w_hh_l1f = (const float*)d_in[8];
    const float* b_l1f    = (const float*)d_in[9];
    const float* w_ih_l1b = (const float*)d_in[10];
    const float* w_hh_l1b = (const float*)d_in[11];
    const float* b_l1b    = (const float*)d_in[12];
    const float* attn_w   = (const float*)d_in[13];
    const float* attn_b   = (const float*)d_in[14];
    const float* head_w   = (const float*)d_in[15];
    const float* head_b   = (const float*)d_in[16];
    float* out = (float*)d_out;

    float *xpf, *xpb, *h0, *h1, *ctx, *ev;
    cudaGetSymbolAddress((void**)&xpf, g_xpf);
    cudaGetSymbolAddress((void**)&xpb, g_xpb);
    cudaGetSymbolAddress((void**)&h0,  g_h0);
    cudaGetSymbolAddress((void**)&h1,  g_h1);
    cudaGetSymbolAddress((void**)&ctx, g_ctx);
    cudaGetSymbolAddress((void**)&ev,  g_e);

    const int M = BATCH * SEQ;   // 32768

    cudaFuncSetAttribute(lstm_scan_cl, cudaFuncAttributeMaxDynamicSharedMemorySize, SCAN_SMEM);
    cudaFuncSetAttribute(mma_gemm,     cudaFuncAttributeMaxDynamicSharedMemorySize, GEMM_SMEM);

    // layer 0 input projections: [32768,128] x [1024,128]^T -> [32768,1024]
    {
        dim3 grid(M / 128, G4 / 128);
        mma_gemm<<<grid, 512, GEMM_SMEM>>>(x, w_ih_l0f, b_l0f, xpf, G4, DIN);
        mma_gemm<<<grid, 512, GEMM_SMEM>>>(x, w_ih_l0b, b_l0b, xpb, G4, DIN);
    }
    // layer 0 scan: grid (slice=8, batchgroup=8, dir=2), cluster (8,1,1)
    {
        dim3 grid(8, 8, 2);
        lstm_scan_cl<<<grid, 256, SCAN_SMEM>>>(xpf, xpb, w_hh_l0f, w_hh_l0b, h0);
    }
    // layer 1 input projections: K=512
    {
        dim3 grid(M / 128, G4 / 128);
        mma_gemm<<<grid, 512, GEMM_SMEM>>>(h0, w_ih_l1f, b_l1f, xpf, G4, H2);
        mma_gemm<<<grid, 512, GEMM_SMEM>>>(h0, w_ih_l1b, b_l1b, xpb, G4, H2);
    }
    // layer 1 scan
    {
        dim3 grid(8, 8, 2);
        lstm_scan_cl<<<grid, 256, SCAN_SMEM>>>(xpf, xpb, w_hh_l1f, w_hh_l1b, h1);
    }
    // attention + running softmax context
    attn_scores<<<BATCH, 256>>>(h1, attn_w, attn_b, ev);
    {
        dim3 grid(BATCH, 4);
        ctx_kernel<<<grid, 128>>>(h1, ev, ctx);
    }
    // head: [32768,512] x [128,512]^T + head_b -> out [32768,128]
    {
        dim3 grid(M / 128, DIN / 128);
        mma_gemm<<<grid, 512, GEMM_SMEM>>>(ctx, head_w, head_b, out, DIN, H2);
    }
}

// round 8
// speedup vs baseline: 1.9672x; 1.9672x over previous
#include <cuda_runtime.h>
#include <math.h>
#include <stdint.h>

#define BATCH 32
#define SEQ   1024
#define DIN   128
#define HID   256
#define G4    1024   // 4*H
#define H2    512    // 2*H

// ---------------- scratch (device globals; no allocation allowed) ----------------
__device__ float  g_xpf[(size_t)BATCH * SEQ * G4];   // 128 MB
__device__ float  g_xpb[(size_t)BATCH * SEQ * G4];   // 128 MB
__device__ float  g_h0 [(size_t)BATCH * SEQ * H2];   // 64 MB
__device__ float  g_h1 [(size_t)BATCH * SEQ * H2];   // 64 MB
__device__ float  g_ctx[(size_t)BATCH * SEQ * H2];   // 64 MB
__device__ float  g_e  [BATCH * SEQ];

// ---------------- helpers ----------------
__device__ __forceinline__ uint32_t smem_u32(const void* p) {
    uint32_t a;
    asm("{ .reg .u64 t; cvta.to.shared.u64 t, %1; cvt.u32.u64 %0, t; }" : "=r"(a) : "l"(p));
    return a;
}
__device__ __forceinline__ uint32_t cvt_tf32(float x) {
    uint32_t r; asm("cvt.rna.tf32.f32 %0, %1;" : "=r"(r) : "f"(x)); return r;
}
__device__ __forceinline__ void mma8(float* d, const uint32_t* a, const uint32_t* b) {
    asm volatile("mma.sync.aligned.m16n8k8.row.col.f32.tf32.tf32.f32 "
        "{%0,%1,%2,%3}, {%4,%5,%6,%7}, {%8,%9}, {%0,%1,%2,%3};"
        : "+f"(d[0]), "+f"(d[1]), "+f"(d[2]), "+f"(d[3])
        : "r"(a[0]), "r"(a[1]), "r"(a[2]), "r"(a[3]), "r"(b[0]), "r"(b[1]));
}

#define MBAR_INIT(a, c) \
    asm volatile("mbarrier.init.shared.b64 [%0], %1;" :: "r"(a), "r"(c) : "memory")
#define MBAR_ARM_TX(a, tx) \
    asm volatile("mbarrier.arrive.expect_tx.shared.b64 _, [%0], %1;" :: "r"(a), "r"(tx) : "memory")
#define MBAR_WAIT(a, ph) do {                                                   \
    uint32_t _m = (a); uint32_t _p = (ph);                                      \
    asm volatile(                                                               \
        "{\n\t.reg .pred P1;\n\t"                                              \
        "WL_%=:\n\t"                                                            \
        "mbarrier.try_wait.parity.acquire.cta.shared::cta.b64 P1, [%0], %1, 0x989680;\n\t" \
        "@P1 bra.uni WD_%=;\n\t"                                                \
        "bra.uni WL_%=;\n\t"                                                    \
        "WD_%=:\n\t}"                                                           \
        :: "r"(_m), "r"(_p) : "memory");                                        \
} while (0)

// ---------------- tf32 split-precision GEMM via mma.sync (R7 version, kept) ----------------
#define BUF_U32   16384
#define GEMM_SMEM (2 * 65536)

__device__ __forceinline__ void g_ldg(const float* __restrict__ A, const float* __restrict__ W,
                                      int m0, int n0, int K, int kbase, int tid,
                                      float4* aR, float4* bR) {
#pragma unroll
    for (int i = 0; i < 2; i++) {
        int lin = tid + i * 512;
        int row = lin >> 3, cg = lin & 7;
        aR[i] = *(const float4*)&A[(size_t)(m0 + row) * K + kbase + cg * 4];
        bR[i] = *(const float4*)&W[(size_t)(n0 + row) * K + kbase + cg * 4];
    }
}

__device__ __forceinline__ void g_stage(uint32_t* buf, const float4* aR, const float4* bR, int tid) {
    uint32_t* Ah = buf;
    uint32_t* Al = buf + 4096;
    uint32_t* Bh = buf + 8192;
    uint32_t* Bl = buf + 12288;
#pragma unroll
    for (int i = 0; i < 2; i++) {
        int lin = tid + i * 512;
        int row = lin >> 3, cg = lin & 7;
        float av[4] = { aR[i].x, aR[i].y, aR[i].z, aR[i].w };
        float wv[4] = { bR[i].x, bR[i].y, bR[i].z, bR[i].w };
#pragma unroll
        for (int j = 0; j < 4; j++) {
            int col = cg * 4 + j;
            int ks = col >> 3, c8 = col & 7, tig = c8 & 3, half = c8 >> 2;
            int lane = ((row & 7) << 2) | tig;
            int regA = ((row >> 3) & 1) | (half << 1);
            int idxA = ((ks * 8 + (row >> 4)) * 32 + lane) * 4 + regA;
            uint32_t hi = cvt_tf32(av[j]);
            uint32_t lo = cvt_tf32(av[j] - __uint_as_float(hi));
            Ah[idxA] = hi; Al[idxA] = lo;
            int idxB = ((ks * 16 + (row >> 3)) * 32 + lane) * 2 + half;
            hi = cvt_tf32(wv[j]);
            lo = cvt_tf32(wv[j] - __uint_as_float(hi));
            Bh[idxB] = hi; Bl[idxB] = lo;
        }
    }
}

__global__ void __launch_bounds__(512, 1) mma_gemm(const float* __restrict__ A,
                                                   const float* __restrict__ W,
                                                   const float* __restrict__ bias,
                                                   float* __restrict__ C,
                                                   int Nld, int K) {
    extern __shared__ uint32_t sm[];
    int tid = threadIdx.x;
    int lane = tid & 31;
    int warp = tid >> 5;
    int wm = warp >> 2, wn = warp & 3;
    int m0 = blockIdx.x * 128, n0 = blockIdx.y * 128;

    float acc[2][4][4];
#pragma unroll
    for (int a = 0; a < 2; a++)
#pragma unroll
        for (int b = 0; b < 4; b++)
#pragma unroll
            for (int c = 0; c < 4; c++) acc[a][b][c] = 0.f;

    float4 aR[2], bR[2];
    g_ldg(A, W, m0, n0, K, 0, tid, aR, bR);
    g_stage(sm, aR, bR, tid);
    __syncthreads();

    const int KT = K / 32;
    for (int kt = 0; kt < KT; kt++) {
        if (kt + 1 < KT) g_ldg(A, W, m0, n0, K, (kt + 1) * 32, tid, aR, bR);

        const uint32_t* buf = sm + (kt & 1) * BUF_U32;
        const uint32_t* Ah = buf;
        const uint32_t* Al = buf + 4096;
        const uint32_t* Bh = buf + 8192;
        const uint32_t* Bl = buf + 12288;
#pragma unroll
        for (int ks = 0; ks < 4; ks++) {
            uint32_t fAh[2][4], fAl[2][4], fBh[4][2], fBl[4][2];
#pragma unroll
            for (int mf = 0; mf < 2; mf++) {
                uint4 v = *(const uint4*)&Ah[((ks * 8 + wm * 2 + mf) * 32 + lane) * 4];
                fAh[mf][0] = v.x; fAh[mf][1] = v.y; fAh[mf][2] = v.z; fAh[mf][3] = v.w;
                uint4 u = *(const uint4*)&Al[((ks * 8 + wm * 2 + mf) * 32 + lane) * 4];
                fAl[mf][0] = u.x; fAl[mf][1] = u.y; fAl[mf][2] = u.z; fAl[mf][3] = u.w;
            }
#pragma unroll
            for (int nf = 0; nf < 4; nf++) {
                uint2 v = *(const uint2*)&Bh[((ks * 16 + wn * 4 + nf) * 32 + lane) * 2];
                fBh[nf][0] = v.x; fBh[nf][1] = v.y;
                uint2 u = *(const uint2*)&Bl[((ks * 16 + wn * 4 + nf) * 32 + lane) * 2];
                fBl[nf][0] = u.x; fBl[nf][1] = u.y;
            }
#pragma unroll
            for (int mf = 0; mf < 2; mf++)
#pragma unroll
                for (int nf = 0; nf < 4; nf++) {
                    mma8(acc[mf][nf], fAh[mf], fBh[nf]);
                    mma8(acc[mf][nf], fAh[mf], fBl[nf]);
                    mma8(acc[mf][nf], fAl[mf], fBh[nf]);
                }
        }
        if (kt + 1 < KT) g_stage(sm + ((kt + 1) & 1) * BUF_U32, aR, bR, tid);
        __syncthreads();
    }

    int g = lane >> 2, tig = lane & 3;
#pragma unroll
    for (int mf = 0; mf < 2; mf++) {
#pragma unroll
        for (int nf = 0; nf < 4; nf++) {
            int row = m0 + wm * 32 + mf * 16 + g;
            int col = n0 + wn * 32 + nf * 8 + tig * 2;
            float b0 = bias[col], b1 = bias[col + 1];
            float2 v0 = make_float2(acc[mf][nf][0] + b0, acc[mf][nf][1] + b1);
            float2 v1 = make_float2(acc[mf][nf][2] + b0, acc[mf][nf][3] + b1);
            *(float2*)&C[(size_t)row * Nld + col]       = v0;
            *(float2*)&C[(size_t)(row + 8) * Nld + col] = v1;
        }
    }
}

// ---------------- f32x2 packed-FMA helpers ----------------
__device__ __forceinline__ unsigned long long ffma2(unsigned long long a,
                                                    unsigned long long b,
                                                    unsigned long long c) {
    unsigned long long d;
    asm("fma.rn.f32x2 %0, %1, %2, %3;" : "=l"(d) : "l"(a), "l"(b), "l"(c));
    return d;
}
__device__ __forceinline__ void unpack2(unsigned long long v, float& x, float& y) {
    asm("mov.b64 {%0, %1}, %2;" : "=f"(x), "=f"(y) : "l"(v));
}
__device__ __forceinline__ float sigm_fast(float x) { return 1.f / (1.f + __expf(-x)); }
__device__ __forceinline__ float tanh_fast(float x) { return 2.f / (1.f + __expf(-2.f * x)) - 1.f; }

// ---------------- clustered LSTM scan v4: R6 compute + mbarrier pipeline ----------------
// Cluster of 8 CTAs (unit slices) per (dir, batch-group of 4). 128 threads.
// Weights resident in SMEM (float2 even/odd-k pairs, slot kp*128 + u*4 + gate).
// h double buffer [2][kp:128][b:4] float2 at SMEM_H_OFF.
// Sync: per-step tx-counting mbarriers (4096 B/step expected), h delivered via
// st.async.shared::cluster.mbarrier::complete_tx — no cluster barrier in loop.
#define SMEM_H_OFF   131072
#define SMEM_MB      (SMEM_H_OFF + 8192)
#define SCAN_SMEM    (SMEM_MB + 64)
#define STEP_TX      4096

__global__ void __launch_bounds__(128, 1) __cluster_dims__(8, 1, 1)
lstm_scan_cl(const float* __restrict__ xpf,
             const float* __restrict__ xpb,
             const float* __restrict__ whh_f,
             const float* __restrict__ whh_b,
             float* __restrict__ out) {
    extern __shared__ char smem[];
    uint32_t smem_base = smem_u32(smem);

    int slice = blockIdx.x;           // 0..7 cluster rank = unit slice
    int bg    = blockIdx.y;           // 0..7 batch group (4 batches)
    int d     = blockIdx.z;           // 0 fw, 1 bw
    const float* xp = d ? xpb : xpf;
    const float* W  = d ? whh_b : whh_f;

    int tid = threadIdx.x;
    int u  = tid >> 2;                // 0..31 local unit
    int b  = tid & 3;                 // 0..3 local batch
    int ug = slice * 32 + u;
    int bglob = bg * 4 + b;

    // resident weight slice: slot kp*128 + u*4 + gate = (w[g*256+ug][2kp], [2kp+1])
    float2* wsh = (float2*)smem;
    for (int i = tid; i < 128 * 32 * 4; i += 128) {
        int g  = i & 3;
        int uu = (i >> 2) & 31;
        int kp = i >> 7;
        int row = g * 256 + slice * 32 + uu;
        wsh[i] = *(const float2*)&W[(size_t)row * HID + 2 * kp];
    }
    float2* hsh = (float2*)(smem + SMEM_H_OFF);
    for (int i = tid; i < 1024; i += 128) hsh[i] = make_float2(0.f, 0.f);
    if (tid == 0) {
        MBAR_INIT(smem_base + SMEM_MB,     1);
        MBAR_INIT(smem_base + SMEM_MB + 8, 1);
        // pre-arm both barriers for their first phase
        MBAR_ARM_TX(smem_base + SMEM_MB,     STEP_TX);
        MBAR_ARM_TX(smem_base + SMEM_MB + 8, STEP_TX);
    }
    __syncthreads();

    // precompute remote data + mbar addresses (mapa hoisted)
    uint32_t ra[8], rm[8];
    {
        uint32_t la = smem_base + SMEM_H_OFF + (uint32_t)(((ug >> 1) * 4 + b) * 8 + (ug & 1) * 4);
        uint32_t lm = smem_base + SMEM_MB;
#pragma unroll
        for (int cta = 0; cta < 8; cta++) {
            asm("mapa.shared::cluster.u32 %0, %1, %2;" : "=r"(ra[cta]) : "r"(la), "r"(cta));
            asm("mapa.shared::cluster.u32 %0, %1, %2;" : "=r"(rm[cta]) : "r"(lm), "r"(cta));
        }
    }

    // one-time cluster sync: inits/arms/zeroed buffers visible everywhere
    asm volatile("barrier.cluster.arrive.aligned;" ::: "memory");
    asm volatile("barrier.cluster.wait.aligned;" ::: "memory");

    const unsigned long long* wq = (const unsigned long long*)smem;
    const unsigned long long* hbase = (const unsigned long long*)(smem + SMEM_H_OFF);
    const unsigned long long* wrow = wq + (size_t)u * 4;

    float c = 0.f;
    int ph0 = 0, ph1 = 0;

    for (int t = 0; t < SEQ; t++) {
        int s = d ? (SEQ - 1 - t) : t;
        const float* xr = xp + ((size_t)bglob * SEQ + s) * G4;
        float xi = xr[ug];
        float xf = xr[ug + 256];
        float xg = xr[ug + 512];
        float xo = xr[ug + 768];

        if (t) {
            if ((t & 1) == 0) {
                MBAR_WAIT(smem_base + SMEM_MB, ph0); ph0 ^= 1;
                if (tid == 0) MBAR_ARM_TX(smem_base + SMEM_MB, STEP_TX);
            } else {
                MBAR_WAIT(smem_base + SMEM_MB + 8, ph1); ph1 ^= 1;
                if (tid == 0) MBAR_ARM_TX(smem_base + SMEM_MB + 8, STEP_TX);
            }
        }

        const unsigned long long* hrow = hbase + (size_t)(t & 1) * 512 + b;

        unsigned long long ai2 = 0ull, af2 = 0ull, ag2 = 0ull, ao2 = 0ull;
#pragma unroll 4
        for (int kp = 0; kp < 128; kp++) {
            unsigned long long h2 = hrow[kp * 4];
            const unsigned long long* wk = wrow + (size_t)kp * 128;
            ai2 = ffma2(h2, wk[0], ai2);
            af2 = ffma2(h2, wk[1], af2);
            ag2 = ffma2(h2, wk[2], ag2);
            ao2 = ffma2(h2, wk[3], ao2);
        }
        float lo, hi;
        unpack2(ai2, lo, hi); float ai = xi + lo + hi;
        unpack2(af2, lo, hi); float af = xf + lo + hi;
        unpack2(ag2, lo, hi); float ag = xg + lo + hi;
        unpack2(ao2, lo, hi); float ao = xo + lo + hi;

        float ig = sigm_fast(ai);
        float fg = sigm_fast(af);
        float gg = tanh_fast(ag);
        float og = sigm_fast(ao);
        c = fg * c + ig * gg;
        float h = og * tanh_fast(c);

        if (t + 1 < SEQ) {
            uint32_t bo = (uint32_t)(((t + 1) & 1) * 4096);
            uint32_t mo = (uint32_t)(((t + 1) & 1) * 8);
#pragma unroll
            for (int cta = 0; cta < 8; cta++)
                asm volatile(
                    "st.async.shared::cluster.mbarrier::complete_tx::bytes.f32 [%0], %1, [%2];"
                    :: "r"(ra[cta] + bo), "f"(h), "r"(rm[cta] + mo) : "memory");
        }
        out[((size_t)bglob * SEQ + s) * H2 + d * HID + ug] = h;
    }

    asm volatile("barrier.cluster.arrive.aligned;" ::: "memory");
    asm volatile("barrier.cluster.wait.aligned;" ::: "memory");
}

// ---------------- attention scores -> e = exp(s - max_t s) ----------------
__global__ void __launch_bounds__(256) attn_scores(const float* __restrict__ h,
                                                   const float* __restrict__ attn_w,
                                                   const float* __restrict__ attn_b,
                                                   float* __restrict__ e_out) {
    int b = blockIdx.x;
    int tid = threadIdx.x;
    __shared__ float sc[SEQ];
    __shared__ float red[256];
    __shared__ float wsh[H2];
    wsh[tid]       = attn_w[tid];
    wsh[tid + 256] = attn_w[tid + 256];
    __syncthreads();
    float ab = attn_b[0];
    float mx = -1e30f;
    for (int t = tid; t < SEQ; t += 256) {
        const float* hr = h + ((size_t)b * SEQ + t) * H2;
        float acc = 0.f;
#pragma unroll 4
        for (int cch = 0; cch < H2; cch += 4) {
            float4 hv = *(const float4*)&hr[cch];
            acc += hv.x * wsh[cch] + hv.y * wsh[cch + 1] + hv.z * wsh[cch + 2] + hv.w * wsh[cch + 3];
        }
        acc += ab;
        sc[t] = acc;
        mx = fmaxf(mx, acc);
    }
    red[tid] = mx;
    __syncthreads();
    for (int s = 128; s > 0; s >>= 1) {
        if (tid < s) red[tid] = fmaxf(red[tid], red[tid + s]);
        __syncthreads();
    }
    mx = red[0];
    for (int t = tid; t < SEQ; t += 256)
        e_out[b * SEQ + t] = expf(sc[t] - mx);
}

// ---------------- running-softmax context (4-way channel split) ----------------
__global__ void __launch_bounds__(128) ctx_kernel(const float* __restrict__ h,
                                                  const float* __restrict__ e,
                                                  float* __restrict__ ctx) {
    int b = blockIdx.x;
    int ch = blockIdx.y * 128 + threadIdx.x;
    const float* eb = e + b * SEQ;
    float num = 0.f, den = 0.f;
    for (int t = 0; t < SEQ; t++) {
        float et = eb[t];
        den += et;
        size_t off = ((size_t)b * SEQ + t) * H2 + ch;
        num += et * h[off];
        ctx[off] = num / den;
    }
}

// ---------------- launch ----------------
extern "C" void kernel_launch(void* const* d_in, const int* in_sizes, int n_in,
                              void* d_out, int out_size) {
    const float* x        = (const float*)d_in[0];
    const float* w_ih_l0f = (const float*)d_in[1];
    const float* w_hh_l0f = (const float*)d_in[2];
    const float* b_l0f    = (const float*)d_in[3];
    const float* w_ih_l0b = (const float*)d_in[4];
    const float* w_hh_l0b = (const float*)d_in[5];
    const float* b_l0b    = (const float*)d_in[6];
    const float* w_ih_l1f = (const float*)d_in[7];
    const float* w_hh_l1f = (const float*)d_in[8];
    const float* b_l1f    = (const float*)d_in[9];
    const float* w_ih_l1b = (const float*)d_in[10];
    const float* w_hh_l1b = (const float*)d_in[11];
    const float* b_l1b    = (const float*)d_in[12];
    const float* attn_w   = (const float*)d_in[13];
    const float* attn_b   = (const float*)d_in[14];
    const float* head_w   = (const float*)d_in[15];
    const float* head_b   = (const float*)d_in[16];
    float* out = (float*)d_out;

    float *xpf, *xpb, *h0, *h1, *ctx, *ev;
    cudaGetSymbolAddress((void**)&xpf, g_xpf);
    cudaGetSymbolAddress((void**)&xpb, g_xpb);
    cudaGetSymbolAddress((void**)&h0,  g_h0);
    cudaGetSymbolAddress((void**)&h1,  g_h1);
    cudaGetSymbolAddress((void**)&ctx, g_ctx);
    cudaGetSymbolAddress((void**)&ev,  g_e);

    const int M = BATCH * SEQ;   // 32768

    cudaFuncSetAttribute(lstm_scan_cl, cudaFuncAttributeMaxDynamicSharedMemorySize, SCAN_SMEM);
    cudaFuncSetAttribute(mma_gemm,     cudaFuncAttributeMaxDynamicSharedMemorySize, GEMM_SMEM);

    // layer 0 input projections: [32768,128] x [1024,128]^T -> [32768,1024]
    {
        dim3 grid(M / 128, G4 / 128);
        mma_gemm<<<grid, 512, GEMM_SMEM>>>(x, w_ih_l0f, b_l0f, xpf, G4, DIN);
        mma_gemm<<<grid, 512, GEMM_SMEM>>>(x, w_ih_l0b, b_l0b, xpb, G4, DIN);
    }
    // layer 0 scan: grid (slice=8, batchgroup=8, dir=2), cluster (8,1,1)
    {
        dim3 grid(8, 8, 2);
        lstm_scan_cl<<<grid, 128, SCAN_SMEM>>>(xpf, xpb, w_hh_l0f, w_hh_l0b, h0);
    }
    // layer 1 input projections: K=512
    {
        dim3 grid(M / 128, G4 / 128);
        mma_gemm<<<grid, 512, GEMM_SMEM>>>(h0, w_ih_l1f, b_l1f, xpf, G4, H2);
        mma_gemm<<<grid, 512, GEMM_SMEM>>>(h0, w_ih_l1b, b_l1b, xpb, G4, H2);
    }
    // layer 1 scan
    {
        dim3 grid(8, 8, 2);
        lstm_scan_cl<<<grid, 128, SCAN_SMEM>>>(xpf, xpb, w_hh_l1f, w_hh_l1b, h1);
    }
    // attention + running softmax context
    attn_scores<<<BATCH, 256>>>(h1, attn_w, attn_b, ev);
    {
        dim3 grid(BATCH, 4);
        ctx_kernel<<<grid, 128>>>(h1, ev, ctx);
    }
    // head: [32768,512] x [128,512]^T + head_b -> out [32768,128]
    {
        dim3 grid(M / 128, DIN / 128);
        mma_gemm<<<grid, 512, GEMM_SMEM>>>(ctx, head_w, head_b, out, DIN, H2);
    }
}